// round 10
// baseline (speedup 1.0000x reference)
#include <cuda_runtime.h>
#include <cuda_fp16.h>
#include <cstdint>
#include <math.h>

#define BB 32
#define LL 2048
#define HH 512
#define CC 50
#define MM (BB * LL)   // 65536

// ---- scratch: half hi/lo planes (allocation-free) ----
__device__ __align__(16) __half g_P1h[(size_t)MM * HH];
__device__ __align__(16) __half g_P1l[(size_t)MM * HH];
__device__ __align__(16) __half g_P12h[(size_t)MM * HH];
__device__ __align__(16) __half g_P12l[(size_t)MM * HH];
__device__ __align__(16) __half g_W1h[HH * HH], g_W1l[HH * HH];
__device__ __align__(16) __half g_W2h[HH * HH], g_W2l[HH * HH];
__device__ __align__(16) __half g_W3h[64 * HH], g_W3l[64 * HH];
__device__ __align__(16) float  g_P3[(size_t)MM * CC];

// ============================================================================
// helpers
// ============================================================================
__device__ __forceinline__ uint32_t s32(const void* p) {
    return (uint32_t)__cvta_generic_to_shared(p);
}
__device__ __forceinline__ void cp16(uint32_t saddr, const void* gaddr) {
    asm volatile("cp.async.cg.shared.global [%0], [%1], 16;" :: "r"(saddr), "l"(gaddr));
}
__device__ __forceinline__ void cp_commit() {
    asm volatile("cp.async.commit_group;" ::: "memory");
}
template <int N>
__device__ __forceinline__ void cp_wait() {
    asm volatile("cp.async.wait_group %0;" :: "n"(N) : "memory");
}
__device__ __forceinline__ void ldsm4(uint32_t* r, uint32_t a) {
    asm volatile("ldmatrix.sync.aligned.m8n8.x4.shared.b16 {%0,%1,%2,%3}, [%4];"
        : "=r"(r[0]), "=r"(r[1]), "=r"(r[2]), "=r"(r[3]) : "r"(a));
}
__device__ __forceinline__ void ldsm4t(uint32_t* r, uint32_t a) {
    asm volatile("ldmatrix.sync.aligned.m8n8.x4.trans.shared.b16 {%0,%1,%2,%3}, [%4];"
        : "=r"(r[0]), "=r"(r[1]), "=r"(r[2]), "=r"(r[3]) : "r"(a));
}
__device__ __forceinline__ void mma16(float* d, const uint32_t* a, const uint32_t* b) {
    asm volatile("mma.sync.aligned.m16n8k16.row.col.f32.f16.f16.f32 "
        "{%0,%1,%2,%3},{%4,%5,%6,%7},{%8,%9},{%0,%1,%2,%3};"
        : "+f"(d[0]), "+f"(d[1]), "+f"(d[2]), "+f"(d[3])
        : "r"(a[0]), "r"(a[1]), "r"(a[2]), "r"(a[3]), "r"(b[0]), "r"(b[1]));
}
__device__ __forceinline__ uint32_t packh2(float a, float b) {
    __half2 h = __floats2half2_rn(a, b);
    return *reinterpret_cast<uint32_t*>(&h);
}
__device__ __forceinline__ void hsplit(float x, float& hf, float& lf) {
    hf = __half2float(__float2half_rn(x));
    lf = x - hf;
}
__device__ __forceinline__ float tanh_fast(float x) {
    float xc = fminf(fmaxf(x, -15.f), 15.f);
    float e = __expf(2.f * xc);
    return 1.f - __fdividef(2.f, e + 1.f);
}
// sent_lens may be int32 or int64. lens in [1, 2048]: for int64 LE, word[1]=0.
__device__ __forceinline__ int load_len(const void* p, int b) {
    const int* w = (const int*)p;
    bool is64 = (w[1] == 0);
    return is64 ? w[2 * b] : w[b];
}

// ============================================================================
// pre-pass: split fp32 weights -> half hi/lo planes (tiny: 1 MB each)
// ============================================================================
__global__ void split_kernel(const float* __restrict__ src, __half* __restrict__ h,
                             __half* __restrict__ l, int n4) {
    for (int i = blockIdx.x * blockDim.x + threadIdx.x; i < n4; i += gridDim.x * blockDim.x) {
        float4 x = ((const float4*)src)[i];
        float h0, l0, h1, l1, h2, l2, h3, l3;
        hsplit(x.x, h0, l0); hsplit(x.y, h1, l1);
        hsplit(x.z, h2, l2); hsplit(x.w, h3, l3);
        *(uint2*)(h + 4 * i) = make_uint2(packh2(h0, h1), packh2(h2, h3));
        *(uint2*)(l + 4 * i) = make_uint2(packh2(l0, l1), packh2(l2, l3));
    }
}
__global__ void split_w3_kernel(const float* __restrict__ src) {
    int i = blockIdx.x * blockDim.x + threadIdx.x;
    if (i >= 64 * HH / 4) return;
    int row = (4 * i) / HH;
    float4 x = make_float4(0.f, 0.f, 0.f, 0.f);
    if (row < CC) x = ((const float4*)src)[i];
    float h0, l0, h1, l1, h2, l2, h3, l3;
    hsplit(x.x, h0, l0); hsplit(x.y, h1, l1);
    hsplit(x.z, h2, l2); hsplit(x.w, h3, l3);
    *(uint2*)(g_W3h + 4 * i) = make_uint2(packh2(h0, h1), packh2(h2, h3));
    *(uint2*)(g_W3l + 4 * i) = make_uint2(packh2(l0, l1), packh2(l2, l3));
}

// ============================================================================
// fp16 3-term GEMM, 256xNT CTA tiles. Term-major MMA order: dependent writes
// to the same accumulator are 32 independent MMAs apart (latency hidden).
// ============================================================================
template <int MODE>
__global__ __launch_bounds__(256, 1) void gemm_f(const float* __restrict__ keys) {
    constexpr int NT = (MODE == 2) ? 64 : 128;
    constexpr int KC = 16;
    constexpr int NCH = HH / KC;          // 32
    constexpr int LD = KC + 8;            // 24 halfs (48B rows, ldsm bank-clean)
    constexpr int BST = 2 * NT * LD;      // halfs per B stage (hi+lo)
    constexpr int ASTF = 2 * 256 * LD;    // halfs per A stage (hi+lo)
    constexpr int MI = (MODE == 2) ? 2 : 4;
    constexpr int NJ = 8;

    extern __shared__ __align__(16) __half sm[];
    __half* Abase = sm + 4 * BST;

    const int tid = threadIdx.x;
    const int lane = tid & 31;
    const int warp = tid >> 5;
    const int row0 = blockIdx.y * 256;
    const int col0 = blockIdx.x * NT;

    const int base_m = (MODE == 2) ? warp * 32 : (warp >> 1) * 64;
    const int base_n = (MODE == 2) ? 0 : (warp & 1) * 64;

    const __half* gAh = (MODE == 1) ? g_P1h : g_P12h;
    const __half* gAl = (MODE == 1) ? g_P1l : g_P12l;
    const __half* gBh = (MODE == 0) ? g_W1h : (MODE == 1) ? g_W2h : g_W3h;
    const __half* gBl = (MODE == 0) ? g_W1l : (MODE == 1) ? g_W2l : g_W3l;

    float acc[MI][NJ][4] = {};
    float4 aR[4];                          // MODE 0 A prefetch registers

    auto loadB = [&](int ch, int s) {
        const int k0 = ch * KC;
        __half* Bh = sm + s * BST;
        __half* Bl = Bh + NT * LD;
        if (NT == 128 || tid < 128) {
            int row = (tid >> 1) & (NT - 1), seg = tid & 1;
            size_t g = (size_t)(col0 + row) * HH + k0 + seg * 8;
            cp16(s32(Bh + row * LD + seg * 8), gBh + g);
            cp16(s32(Bl + row * LD + seg * 8), gBl + g);
        }
    };
    auto loadA = [&](int ch, int s) {       // MODE 1/2 only
        const int k0 = ch * KC;
        __half* Ah = Abase + s * ASTF;
        __half* Al = Ah + 256 * LD;
        int row = tid >> 1, seg = tid & 1;
        size_t g = (size_t)(row0 + row) * HH + k0 + seg * 8;
        cp16(s32(Ah + row * LD + seg * 8), gAh + g);
        cp16(s32(Al + row * LD + seg * 8), gAl + g);
        g = (size_t)(row0 + 128 + row) * HH + k0 + seg * 8;
        cp16(s32(Ah + (128 + row) * LD + seg * 8), gAh + g);
        cp16(s32(Al + (128 + row) * LD + seg * 8), gAl + g);
    };
    auto g2rA = [&](int ch) {               // MODE 0 only
        const int k0 = ch * KC;
#pragma unroll
        for (int i = 0; i < 4; i++) {
            int f = i * 256 + tid, row = f >> 2, seg = f & 3;
            aR[i] = *(const float4*)(keys + (size_t)(row0 + row) * HH + k0 + seg * 4);
        }
    };
    auto r2sA = [&](int s) {                // MODE 0 only
        __half* Ah = Abase + s * ASTF;
        __half* Al = Ah + 256 * LD;
#pragma unroll
        for (int i = 0; i < 4; i++) {
            int f = i * 256 + tid, row = f >> 2, seg = f & 3;
            float h0, l0, h1, l1, h2, l2, h3, l3;
            hsplit(aR[i].x, h0, l0); hsplit(aR[i].y, h1, l1);
            hsplit(aR[i].z, h2, l2); hsplit(aR[i].w, h3, l3);
            *(uint2*)(Ah + row * LD + seg * 4) = make_uint2(packh2(h0, h1), packh2(h2, h3));
            *(uint2*)(Al + row * LD + seg * 4) = make_uint2(packh2(l0, l1), packh2(l2, l3));
        }
    };

    auto compute = [&](int sB, int sA) {
        const __half* Bh0 = sm + sB * BST;
        const __half* Bl0 = Bh0 + NT * LD;
        const __half* Ah0 = Abase + sA * ASTF;
        const __half* Al0 = Ah0 + 256 * LD;
        uint32_t fAh[MI][4], fAl[MI][4], bh[4][4], bl[4][4];
#pragma unroll
        for (int mi = 0; mi < MI; mi++) {
            int row = base_m + mi * 16 + (lane & 15);
            int off = row * LD + ((lane >> 4) << 3);
            ldsm4(fAh[mi], s32(Ah0 + off));
            ldsm4(fAl[mi], s32(Al0 + off));
        }
#pragma unroll
        for (int p = 0; p < 4; p++) {
            int n = base_n + p * 16 + (lane & 7) + ((lane >> 4) << 3);
            int off = n * LD + (((lane >> 3) & 1) << 3);
            ldsm4(bh[p], s32(Bh0 + off));
            ldsm4(bl[p], s32(Bl0 + off));
        }
        // term 1: Ah*Bh — all 32 accumulators (independent)
#pragma unroll
        for (int mi = 0; mi < MI; mi++)
#pragma unroll
            for (int p = 0; p < 4; p++) {
                mma16(acc[mi][2 * p], fAh[mi], bh[p]);
                mma16(acc[mi][2 * p + 1], fAh[mi], bh[p] + 2);
            }
        // term 2: Al*Bh
#pragma unroll
        for (int mi = 0; mi < MI; mi++)
#pragma unroll
            for (int p = 0; p < 4; p++) {
                mma16(acc[mi][2 * p], fAl[mi], bh[p]);
                mma16(acc[mi][2 * p + 1], fAl[mi], bh[p] + 2);
            }
        // term 3: Ah*Bl
#pragma unroll
        for (int mi = 0; mi < MI; mi++)
#pragma unroll
            for (int p = 0; p < 4; p++) {
                mma16(acc[mi][2 * p], fAh[mi], bl[p]);
                mma16(acc[mi][2 * p + 1], fAh[mi], bl[p] + 2);
            }
    };

    // prologue: 3 chunk-groups in flight; MODE 0 pre-stages A(0)
#pragma unroll
    for (int s = 0; s < 3; s++) {
        if (MODE != 0) loadA(s, s);
        loadB(s, s);
        cp_commit();
    }
    if (MODE == 0) { g2rA(0); r2sA(0); }

    for (int ch = 0; ch < NCH; ch++) {
        cp_wait<2>();
        __syncthreads();
        if (ch + 3 < NCH) {
            if (MODE != 0) loadA(ch + 3, (ch + 3) & 3);
            loadB(ch + 3, (ch + 3) & 3);
        }
        cp_commit();
        if (MODE == 0 && ch + 1 < NCH) g2rA(ch + 1);
        compute(ch & 3, (MODE == 0) ? (ch & 1) : (ch & 3));
        if (MODE == 0 && ch + 1 < NCH) r2sA((ch + 1) & 1);
    }

    // ---- epilogue ----
#pragma unroll
    for (int mi = 0; mi < MI; mi++)
#pragma unroll
        for (int j = 0; j < NJ; j++)
#pragma unroll
            for (int hh = 0; hh < 2; hh++) {
                int r = row0 + base_m + mi * 16 + (lane >> 2) + hh * 8;
                int c = col0 + base_n + j * 8 + 2 * (lane & 3);
                float v0 = acc[mi][j][2 * hh], v1 = acc[mi][j][2 * hh + 1];
                if constexpr (MODE == 2) {
                    if (c < CC)
                        *(float2*)(g_P3 + (size_t)r * CC + c) = make_float2(v0, v1);
                } else {
                    size_t off = (size_t)r * HH + c;
                    float t0, t1;
                    if constexpr (MODE == 0) {
                        t0 = tanh_fast(v0); t1 = tanh_fast(v1);
                    } else {
                        float2 pf = __half22float2(*(const __half2*)(g_P1h + off));
                        float2 qf = __half22float2(*(const __half2*)(g_P1l + off));
                        t0 = (pf.x + qf.x) + tanh_fast(v0);
                        t1 = (pf.y + qf.y) + tanh_fast(v1);
                    }
                    float h0, l0, h1, l1;
                    hsplit(t0, h0, l0); hsplit(t1, h1, l1);
                    __half* oh = (MODE == 0) ? g_P1h : g_P12h;
                    __half* ol = (MODE == 0) ? g_P1l : g_P12l;
                    *(uint32_t*)(oh + off) = packh2(h0, h1);
                    *(uint32_t*)(ol + off) = packh2(l0, l1);
                }
            }
}

// ============================================================================
// class_inputs[b,c,h] = sum_l attn[b,l,c] * V[b,l,h]  (term-major MMA order)
// ============================================================================
__global__ __launch_bounds__(256, 1) void classmm_h(const float* __restrict__ attn,
                                                    const float* __restrict__ V,
                                                    float* __restrict__ Out) {
    constexpr int KC = 32;
    constexpr int NCH = LL / KC;    // 64
    constexpr int LDAA = 72;
    constexpr int LDB = 136;
    constexpr int A_ST = KC * LDAA;
    constexpr int B_ST = KC * LDB;
    constexpr int STAGE = 2 * A_ST + 2 * B_ST;
    constexpr int MI = 2;

    extern __shared__ __align__(16) __half sm[];
    const int tid = threadIdx.x, lane = tid & 31, warp = tid >> 5;
    const int b = blockIdx.y;
    const int h0 = blockIdx.x * 128;
    const int base_m = (warp >> 2) * 32;
    const int base_n = (warp & 3) * 32;

    float acc[MI][4][4] = {};
    float2 aA[4]; float4 aB[4];
    const int m2 = tid & 31;
    const int kkA = tid >> 5;

    auto g2r = [&](int ch) {
        const int k0 = ch * KC;
#pragma unroll
        for (int i = 0; i < 4; i++) {
            int kk = kkA + i * 8;
            float2 x = make_float2(0.f, 0.f);
            if (m2 < 25) x = *(const float2*)(attn + ((size_t)b * LL + k0 + kk) * CC + m2 * 2);
            aA[i] = x;
        }
#pragma unroll
        for (int i = 0; i < 4; i++) {
            int f = i * 256 + tid, n4 = f & 31, kk = f >> 5;
            aB[i] = *(const float4*)(V + ((size_t)b * LL + k0 + kk) * HH + h0 + n4 * 4);
        }
    };
    auto r2s = [&](int s) {
        __half* Ah = sm + s * STAGE;
        __half* Al = Ah + A_ST;
        __half* Bh = Al + A_ST;
        __half* Bl = Bh + B_ST;
#pragma unroll
        for (int i = 0; i < 4; i++) {
            int kk = kkA + i * 8;
            float h0_, l0_, h1_, l1_;
            hsplit(aA[i].x, h0_, l0_); hsplit(aA[i].y, h1_, l1_);
            *(uint32_t*)(Ah + kk * LDAA + m2 * 2) = packh2(h0_, h1_);
            *(uint32_t*)(Al + kk * LDAA + m2 * 2) = packh2(l0_, l1_);
        }
#pragma unroll
        for (int i = 0; i < 4; i++) {
            int f = i * 256 + tid, n4 = f & 31, kk = f >> 5;
            float h0_, l0_, h1_, l1_, h2_, l2_, h3_, l3_;
            hsplit(aB[i].x, h0_, l0_); hsplit(aB[i].y, h1_, l1_);
            hsplit(aB[i].z, h2_, l2_); hsplit(aB[i].w, h3_, l3_);
            *(uint2*)(Bh + kk * LDB + n4 * 4) = make_uint2(packh2(h0_, h1_), packh2(h2_, h3_));
            *(uint2*)(Bl + kk * LDB + n4 * 4) = make_uint2(packh2(l0_, l1_), packh2(l2_, l3_));
        }
    };
    auto compute = [&](int s) {
        const __half* Ah = sm + s * STAGE;
        const __half* Al = Ah + A_ST;
        const __half* Bh = Al + A_ST;
        const __half* Bl = Bh + B_ST;
#pragma unroll
        for (int ks = 0; ks < 2; ks++) {
            uint32_t fAh[MI][4], fAl[MI][4], fBh[4][2], fBl[4][2];
#pragma unroll
            for (int mi = 0; mi < MI; mi++) {
                int krow = ks * 16 + (lane & 7) + ((lane >> 4) << 3);
                int moff = base_m + mi * 16 + ((lane >> 3) & 1) * 8;
                int off = krow * LDAA + moff;
                ldsm4t(fAh[mi], s32(Ah + off));
                ldsm4t(fAl[mi], s32(Al + off));
            }
#pragma unroll
            for (int p = 0; p < 2; p++) {
                int krow = ks * 16 + (lane & 7) + (((lane >> 3) & 1) << 3);
                int noff = base_n + p * 16 + ((lane >> 4) << 3);
                int off = krow * LDB + noff;
                uint32_t r[4];
                ldsm4t(r, s32(Bh + off));
                fBh[2 * p][0] = r[0]; fBh[2 * p][1] = r[1];
                fBh[2 * p + 1][0] = r[2]; fBh[2 * p + 1][1] = r[3];
                ldsm4t(r, s32(Bl + off));
                fBl[2 * p][0] = r[0]; fBl[2 * p][1] = r[1];
                fBl[2 * p + 1][0] = r[2]; fBl[2 * p + 1][1] = r[3];
            }
            // term-major: dependent acc writes separated by 8 independent MMAs
#pragma unroll
            for (int mi = 0; mi < MI; mi++)
#pragma unroll
                for (int j = 0; j < 4; j++) mma16(acc[mi][j], fAh[mi], fBh[j]);
#pragma unroll
            for (int mi = 0; mi < MI; mi++)
#pragma unroll
                for (int j = 0; j < 4; j++) mma16(acc[mi][j], fAl[mi], fBh[j]);
#pragma unroll
            for (int mi = 0; mi < MI; mi++)
#pragma unroll
                for (int j = 0; j < 4; j++) mma16(acc[mi][j], fAh[mi], fBl[j]);
        }
    };

    g2r(0); r2s(0); __syncthreads();
    for (int ch = 0; ch < NCH; ch++) {
        const int s = ch & 1;
        if (ch + 1 < NCH) g2r(ch + 1);
        compute(s);
        if (ch + 1 < NCH) r2s(s ^ 1);
        __syncthreads();
    }

#pragma unroll
    for (int mi = 0; mi < MI; mi++)
#pragma unroll
        for (int j = 0; j < 4; j++)
#pragma unroll
            for (int hh = 0; hh < 2; hh++) {
                int c = base_m + mi * 16 + (lane >> 2) + hh * 8;
                int h = h0 + base_n + j * 8 + 2 * (lane & 3);
                if (c < CC)
                    *(float2*)(Out + ((size_t)b * CC + c) * HH + h)
                        = make_float2(acc[mi][j][2 * hh], acc[mi][j][2 * hh + 1]);
            }
}

// ============================================================================
// Fill-at-(len-1) + avgpool3 (count_include_pad=False) + softmax + mask.
// ============================================================================
__global__ __launch_bounds__(128) void pool_softmax_kernel(const void* __restrict__ lens_raw,
                                                           float* __restrict__ attn,
                                                           float* __restrict__ smooth) {
    const int b = blockIdx.y;
    const int l0 = blockIdx.x * 128;
    const int len = load_len(lens_raw, b);

    __shared__ float s[130][CC];
    const int tid = threadIdx.x;

    for (int i = tid; i < 130 * CC; i += 128) {
        int rr = i / CC, c = i - rr * CC;
        int l = l0 - 1 + rr;
        l = max(0, min(l, LL - 1));
        int src = min(l, len - 1);
        s[rr][c] = g_P3[((size_t)b * LL + src) * CC + c];
    }
    __syncthreads();

    const int l = l0 + tid;
    const bool hasL = (l > 0), hasR = (l < LL - 1);
    const float inv = 1.0f / (float)(1 + (hasL ? 1 : 0) + (hasR ? 1 : 0));
    const int rr = tid + 1;

    float v[CC];
    float mx = -1e30f;
#pragma unroll
    for (int c = 0; c < CC; c++) {
        float t = s[rr][c];
        if (hasL) t += s[rr - 1][c];
        if (hasR) t += s[rr + 1][c];
        t *= inv;
        v[c] = t;
        mx = fmaxf(mx, t);
    }
    const size_t base = ((size_t)b * LL + l) * CC;
    float sum = 0.f;
#pragma unroll
    for (int c = 0; c < CC; c++) {
        smooth[base + c] = v[c];
        float e = expf(v[c] - mx);
        v[c] = e;
        sum += e;
    }
    const float isum = (l < len) ? (1.0f / sum) : 0.0f;
#pragma unroll
    for (int c = 0; c < CC; c++) attn[base + c] = v[c] * isum;
}

// ============================================================================
extern "C" void kernel_launch(void* const* d_in, const int* in_sizes, int n_in,
                              void* d_out, int out_size) {
    const float* keys = (const float*)d_in[0];
    const float* vals = (const float*)d_in[1];
    const void*  lens = d_in[2];
    const float* W1 = (const float*)d_in[3];
    const float* W2 = (const float*)d_in[4];
    const float* W3 = (const float*)d_in[5];

    float* attn   = (float*)d_out;                        // (B, L, C)
    float* cls    = attn + (size_t)BB * LL * CC;          // (B, C, H)
    float* smooth = cls + (size_t)BB * CC * HH;           // (B, L, C)

    __half *w1h, *w1l, *w2h, *w2l;
    cudaGetSymbolAddress((void**)&w1h, g_W1h); cudaGetSymbolAddress((void**)&w1l, g_W1l);
    cudaGetSymbolAddress((void**)&w2h, g_W2h); cudaGetSymbolAddress((void**)&w2l, g_W2l);

    const int SM0 = (4 * 2 * 128 * 24 + 2 * 2 * 256 * 24) * 2;  //  98304
    const int SM1 = (4 * 2 * 128 * 24 + 4 * 2 * 256 * 24) * 2;  // 147456
    const int SM2 = (4 * 2 * 64 * 24 + 4 * 2 * 256 * 24) * 2;   // 122880
    const int SMC = 2 * (2 * 32 * 72 + 2 * 32 * 136) * 2;       //  53248
    cudaFuncSetAttribute(gemm_f<0>, cudaFuncAttributeMaxDynamicSharedMemorySize, SM0);
    cudaFuncSetAttribute(gemm_f<1>, cudaFuncAttributeMaxDynamicSharedMemorySize, SM1);
    cudaFuncSetAttribute(gemm_f<2>, cudaFuncAttributeMaxDynamicSharedMemorySize, SM2);
    cudaFuncSetAttribute(classmm_h, cudaFuncAttributeMaxDynamicSharedMemorySize, SMC);

    split_kernel<<<256, 256>>>(W1, w1h, w1l, HH * HH / 4);
    split_kernel<<<256, 256>>>(W2, w2h, w2l, HH * HH / 4);
    split_w3_kernel<<<32, 256>>>(W3);

    gemm_f<0><<<dim3(HH / 128, MM / 256), 256, SM0>>>(keys);
    gemm_f<1><<<dim3(HH / 128, MM / 256), 256, SM1>>>(nullptr);
    gemm_f<2><<<dim3(1, MM / 256), 256, SM2>>>(nullptr);
    pool_softmax_kernel<<<dim3(LL / 128, BB), 128>>>(lens, attn, smooth);
    classmm_h<<<dim3(HH / 128, BB), 256, SMC>>>(attn, vals, cls);
}

// round 11
// speedup vs baseline: 1.2647x; 1.2647x over previous
#include <cuda_runtime.h>
#include <cuda_fp16.h>
#include <cstdint>
#include <math.h>

#define BB 32
#define LL 2048
#define HH 512
#define CC 50
#define MM (BB * LL)   // 65536

// ---- scratch: half planes (allocation-free). A-side keeps hi+lo (2-term
// compensation on A); B/weights keep hi only. ----
__device__ __align__(16) __half g_P1h[(size_t)MM * HH];
__device__ __align__(16) __half g_P1l[(size_t)MM * HH];
__device__ __align__(16) __half g_P12h[(size_t)MM * HH];
__device__ __align__(16) __half g_P12l[(size_t)MM * HH];
__device__ __align__(16) __half g_W1h[HH * HH];
__device__ __align__(16) __half g_W2h[HH * HH];
__device__ __align__(16) __half g_W3h[64 * HH];
__device__ __align__(16) float  g_P3[(size_t)MM * CC];

// ============================================================================
// helpers
// ============================================================================
__device__ __forceinline__ uint32_t s32(const void* p) {
    return (uint32_t)__cvta_generic_to_shared(p);
}
__device__ __forceinline__ void cp16(uint32_t saddr, const void* gaddr) {
    asm volatile("cp.async.cg.shared.global [%0], [%1], 16;" :: "r"(saddr), "l"(gaddr));
}
__device__ __forceinline__ void cp_commit() {
    asm volatile("cp.async.commit_group;" ::: "memory");
}
template <int N>
__device__ __forceinline__ void cp_wait() {
    asm volatile("cp.async.wait_group %0;" :: "n"(N) : "memory");
}
__device__ __forceinline__ void ldsm4(uint32_t* r, uint32_t a) {
    asm volatile("ldmatrix.sync.aligned.m8n8.x4.shared.b16 {%0,%1,%2,%3}, [%4];"
        : "=r"(r[0]), "=r"(r[1]), "=r"(r[2]), "=r"(r[3]) : "r"(a));
}
__device__ __forceinline__ void ldsm4t(uint32_t* r, uint32_t a) {
    asm volatile("ldmatrix.sync.aligned.m8n8.x4.trans.shared.b16 {%0,%1,%2,%3}, [%4];"
        : "=r"(r[0]), "=r"(r[1]), "=r"(r[2]), "=r"(r[3]) : "r"(a));
}
__device__ __forceinline__ void mma16(float* d, const uint32_t* a, const uint32_t* b) {
    asm volatile("mma.sync.aligned.m16n8k16.row.col.f32.f16.f16.f32 "
        "{%0,%1,%2,%3},{%4,%5,%6,%7},{%8,%9},{%0,%1,%2,%3};"
        : "+f"(d[0]), "+f"(d[1]), "+f"(d[2]), "+f"(d[3])
        : "r"(a[0]), "r"(a[1]), "r"(a[2]), "r"(a[3]), "r"(b[0]), "r"(b[1]));
}
__device__ __forceinline__ uint32_t packh2(float a, float b) {
    __half2 h = __floats2half2_rn(a, b);
    return *reinterpret_cast<uint32_t*>(&h);
}
__device__ __forceinline__ void hsplit(float x, float& hf, float& lf) {
    hf = __half2float(__float2half_rn(x));
    lf = x - hf;
}
__device__ __forceinline__ float tanh_fast(float x) {
    float xc = fminf(fmaxf(x, -15.f), 15.f);
    float e = __expf(2.f * xc);
    return 1.f - __fdividef(2.f, e + 1.f);
}
// sent_lens may be int32 or int64. lens in [1, 2048]: for int64 LE, word[1]=0.
__device__ __forceinline__ int load_len(const void* p, int b) {
    const int* w = (const int*)p;
    bool is64 = (w[1] == 0);
    return is64 ? w[2 * b] : w[b];
}

// ============================================================================
// pre-pass: weights -> half hi plane only
// ============================================================================
__global__ void split_hi_kernel(const float* __restrict__ src, __half* __restrict__ h, int n4) {
    for (int i = blockIdx.x * blockDim.x + threadIdx.x; i < n4; i += gridDim.x * blockDim.x) {
        float4 x = ((const float4*)src)[i];
        *(uint2*)(h + 4 * i) = make_uint2(packh2(x.x, x.y), packh2(x.z, x.w));
    }
}
__global__ void split_w3_kernel(const float* __restrict__ src) {
    int i = blockIdx.x * blockDim.x + threadIdx.x;
    if (i >= 64 * HH / 4) return;
    int row = (4 * i) / HH;
    float4 x = make_float4(0.f, 0.f, 0.f, 0.f);
    if (row < CC) x = ((const float4*)src)[i];
    *(uint2*)(g_W3h + 4 * i) = make_uint2(packh2(x.x, x.y), packh2(x.z, x.w));
}

// ============================================================================
// fp16 2-term GEMM (A split hi/lo, B hi only), 256xNT CTA tiles.
// D(256 x NT) = A(256 x 512) * W^T ; KC = 16, 32 chunks.
// MODE 0: A = keys fp32 (LDG+split), B = g_W1h, epi: split(tanh(D)) -> g_P1
// MODE 1: A = g_P1 planes,           B = g_W2h, epi: split(P1+tanh(D)) -> g_P12
// MODE 2: A = g_P12 planes, NT=64,   B = g_W3h, epi: D -> g_P3 (c < 50)
// ============================================================================
template <int MODE>
__global__ __launch_bounds__(256, 1) void gemm_f(const float* __restrict__ keys) {
    constexpr int NT = (MODE == 2) ? 64 : 128;
    constexpr int KC = 16;
    constexpr int NCH = HH / KC;          // 32
    constexpr int LD = KC + 8;            // 24 halfs (48B rows, ldsm bank-clean)
    constexpr int BST = NT * LD;          // halfs per B stage (hi only)
    constexpr int ASTF = 2 * 256 * LD;    // halfs per A stage (hi+lo)
    constexpr int MI = (MODE == 2) ? 2 : 4;
    constexpr int NJ = 8;

    extern __shared__ __align__(16) __half sm[];
    __half* Abase = sm + 4 * BST;

    const int tid = threadIdx.x;
    const int lane = tid & 31;
    const int warp = tid >> 5;
    const int row0 = blockIdx.y * 256;
    const int col0 = blockIdx.x * NT;

    const int base_m = (MODE == 2) ? warp * 32 : (warp >> 1) * 64;
    const int base_n = (MODE == 2) ? 0 : (warp & 1) * 64;

    const __half* gAh = (MODE == 1) ? g_P1h : g_P12h;
    const __half* gAl = (MODE == 1) ? g_P1l : g_P12l;
    const __half* gBh = (MODE == 0) ? g_W1h : (MODE == 1) ? g_W2h : g_W3h;

    float acc[MI][NJ][4] = {};
    float4 aR[4];                          // MODE 0 A prefetch registers

    auto loadB = [&](int ch, int s) {
        const int k0 = ch * KC;
        __half* Bh = sm + s * BST;
        if (NT == 128 || tid < 128) {
            int row = (tid >> 1) & (NT - 1), seg = tid & 1;
            size_t g = (size_t)(col0 + row) * HH + k0 + seg * 8;
            cp16(s32(Bh + row * LD + seg * 8), gBh + g);
        }
    };
    auto loadA = [&](int ch, int s) {       // MODE 1/2 only
        const int k0 = ch * KC;
        __half* Ah = Abase + s * ASTF;
        __half* Al = Ah + 256 * LD;
        int row = tid >> 1, seg = tid & 1;
        size_t g = (size_t)(row0 + row) * HH + k0 + seg * 8;
        cp16(s32(Ah + row * LD + seg * 8), gAh + g);
        cp16(s32(Al + row * LD + seg * 8), gAl + g);
        g = (size_t)(row0 + 128 + row) * HH + k0 + seg * 8;
        cp16(s32(Ah + (128 + row) * LD + seg * 8), gAh + g);
        cp16(s32(Al + (128 + row) * LD + seg * 8), gAl + g);
    };
    auto g2rA = [&](int ch) {               // MODE 0 only
        const int k0 = ch * KC;
#pragma unroll
        for (int i = 0; i < 4; i++) {
            int f = i * 256 + tid, row = f >> 2, seg = f & 3;
            aR[i] = *(const float4*)(keys + (size_t)(row0 + row) * HH + k0 + seg * 4);
        }
    };
    auto r2sA = [&](int s) {                // MODE 0 only
        __half* Ah = Abase + s * ASTF;
        __half* Al = Ah + 256 * LD;
#pragma unroll
        for (int i = 0; i < 4; i++) {
            int f = i * 256 + tid, row = f >> 2, seg = f & 3;
            float h0, l0, h1, l1, h2, l2, h3, l3;
            hsplit(aR[i].x, h0, l0); hsplit(aR[i].y, h1, l1);
            hsplit(aR[i].z, h2, l2); hsplit(aR[i].w, h3, l3);
            *(uint2*)(Ah + row * LD + seg * 4) = make_uint2(packh2(h0, h1), packh2(h2, h3));
            *(uint2*)(Al + row * LD + seg * 4) = make_uint2(packh2(l0, l1), packh2(l2, l3));
        }
    };

    auto compute = [&](int sB, int sA) {
        const __half* Bh0 = sm + sB * BST;
        const __half* Ah0 = Abase + sA * ASTF;
        const __half* Al0 = Ah0 + 256 * LD;
        uint32_t fAh[MI][4], fAl[MI][4], bh[4][4];
#pragma unroll
        for (int mi = 0; mi < MI; mi++) {
            int row = base_m + mi * 16 + (lane & 15);
            int off = row * LD + ((lane >> 4) << 3);
            ldsm4(fAh[mi], s32(Ah0 + off));
            ldsm4(fAl[mi], s32(Al0 + off));
        }
#pragma unroll
        for (int p = 0; p < 4; p++) {
            int n = base_n + p * 16 + (lane & 7) + ((lane >> 4) << 3);
            int off = n * LD + (((lane >> 3) & 1) << 3);
            ldsm4(bh[p], s32(Bh0 + off));
        }
        // term 1: Ah*Bh — all accumulators, independent
#pragma unroll
        for (int mi = 0; mi < MI; mi++)
#pragma unroll
            for (int p = 0; p < 4; p++) {
                mma16(acc[mi][2 * p], fAh[mi], bh[p]);
                mma16(acc[mi][2 * p + 1], fAh[mi], bh[p] + 2);
            }
        // term 2: Al*Bh
#pragma unroll
        for (int mi = 0; mi < MI; mi++)
#pragma unroll
            for (int p = 0; p < 4; p++) {
                mma16(acc[mi][2 * p], fAl[mi], bh[p]);
                mma16(acc[mi][2 * p + 1], fAl[mi], bh[p] + 2);
            }
    };

    // prologue: 3 chunk-groups in flight; MODE 0 pre-stages A(0)
#pragma unroll
    for (int s = 0; s < 3; s++) {
        if (MODE != 0) loadA(s, s);
        loadB(s, s);
        cp_commit();
    }
    if (MODE == 0) { g2rA(0); r2sA(0); }

    for (int ch = 0; ch < NCH; ch++) {
        cp_wait<2>();
        __syncthreads();
        if (ch + 3 < NCH) {
            if (MODE != 0) loadA(ch + 3, (ch + 3) & 3);
            loadB(ch + 3, (ch + 3) & 3);
        }
        cp_commit();
        if (MODE == 0 && ch + 1 < NCH) g2rA(ch + 1);
        compute(ch & 3, (MODE == 0) ? (ch & 1) : (ch & 3));
        if (MODE == 0 && ch + 1 < NCH) r2sA((ch + 1) & 1);
    }

    // ---- epilogue ----
#pragma unroll
    for (int mi = 0; mi < MI; mi++)
#pragma unroll
        for (int j = 0; j < NJ; j++)
#pragma unroll
            for (int hh = 0; hh < 2; hh++) {
                int r = row0 + base_m + mi * 16 + (lane >> 2) + hh * 8;
                int c = col0 + base_n + j * 8 + 2 * (lane & 3);
                float v0 = acc[mi][j][2 * hh], v1 = acc[mi][j][2 * hh + 1];
                if constexpr (MODE == 2) {
                    if (c < CC)
                        *(float2*)(g_P3 + (size_t)r * CC + c) = make_float2(v0, v1);
                } else {
                    size_t off = (size_t)r * HH + c;
                    float t0, t1;
                    if constexpr (MODE == 0) {
                        t0 = tanh_fast(v0); t1 = tanh_fast(v1);
                    } else {
                        float2 pf = __half22float2(*(const __half2*)(g_P1h + off));
                        float2 qf = __half22float2(*(const __half2*)(g_P1l + off));
                        t0 = (pf.x + qf.x) + tanh_fast(v0);
                        t1 = (pf.y + qf.y) + tanh_fast(v1);
                    }
                    float h0, l0, h1, l1;
                    hsplit(t0, h0, l0); hsplit(t1, h1, l1);
                    __half* oh = (MODE == 0) ? g_P1h : g_P12h;
                    __half* ol = (MODE == 0) ? g_P1l : g_P12l;
                    *(uint32_t*)(oh + off) = packh2(h0, h1);
                    *(uint32_t*)(ol + off) = packh2(l0, l1);
                }
            }
}

// ============================================================================
// class_inputs[b,c,h] = sum_l attn[b,l,c] * V[b,l,h]  (full 3-term, unchanged)
// ============================================================================
__global__ __launch_bounds__(256, 1) void classmm_h(const float* __restrict__ attn,
                                                    const float* __restrict__ V,
                                                    float* __restrict__ Out) {
    constexpr int KC = 32;
    constexpr int NCH = LL / KC;    // 64
    constexpr int LDAA = 72;
    constexpr int LDB = 136;
    constexpr int A_ST = KC * LDAA;
    constexpr int B_ST = KC * LDB;
    constexpr int STAGE = 2 * A_ST + 2 * B_ST;
    constexpr int MI = 2;

    extern __shared__ __align__(16) __half sm[];
    const int tid = threadIdx.x, lane = tid & 31, warp = tid >> 5;
    const int b = blockIdx.y;
    const int h0 = blockIdx.x * 128;
    const int base_m = (warp >> 2) * 32;
    const int base_n = (warp & 3) * 32;

    float acc[MI][4][4] = {};
    float2 aA[4]; float4 aB[4];
    const int m2 = tid & 31;
    const int kkA = tid >> 5;

    auto g2r = [&](int ch) {
        const int k0 = ch * KC;
#pragma unroll
        for (int i = 0; i < 4; i++) {
            int kk = kkA + i * 8;
            float2 x = make_float2(0.f, 0.f);
            if (m2 < 25) x = *(const float2*)(attn + ((size_t)b * LL + k0 + kk) * CC + m2 * 2);
            aA[i] = x;
        }
#pragma unroll
        for (int i = 0; i < 4; i++) {
            int f = i * 256 + tid, n4 = f & 31, kk = f >> 5;
            aB[i] = *(const float4*)(V + ((size_t)b * LL + k0 + kk) * HH + h0 + n4 * 4);
        }
    };
    auto r2s = [&](int s) {
        __half* Ah = sm + s * STAGE;
        __half* Al = Ah + A_ST;
        __half* Bh = Al + A_ST;
        __half* Bl = Bh + B_ST;
#pragma unroll
        for (int i = 0; i < 4; i++) {
            int kk = kkA + i * 8;
            float h0_, l0_, h1_, l1_;
            hsplit(aA[i].x, h0_, l0_); hsplit(aA[i].y, h1_, l1_);
            *(uint32_t*)(Ah + kk * LDAA + m2 * 2) = packh2(h0_, h1_);
            *(uint32_t*)(Al + kk * LDAA + m2 * 2) = packh2(l0_, l1_);
        }
#pragma unroll
        for (int i = 0; i < 4; i++) {
            int f = i * 256 + tid, n4 = f & 31, kk = f >> 5;
            float h0_, l0_, h1_, l1_, h2_, l2_, h3_, l3_;
            hsplit(aB[i].x, h0_, l0_); hsplit(aB[i].y, h1_, l1_);
            hsplit(aB[i].z, h2_, l2_); hsplit(aB[i].w, h3_, l3_);
            *(uint2*)(Bh + kk * LDB + n4 * 4) = make_uint2(packh2(h0_, h1_), packh2(h2_, h3_));
            *(uint2*)(Bl + kk * LDB + n4 * 4) = make_uint2(packh2(l0_, l1_), packh2(l2_, l3_));
        }
    };
    auto compute = [&](int s) {
        const __half* Ah = sm + s * STAGE;
        const __half* Al = Ah + A_ST;
        const __half* Bh = Al + A_ST;
        const __half* Bl = Bh + B_ST;
#pragma unroll
        for (int ks = 0; ks < 2; ks++) {
            uint32_t fAh[MI][4], fAl[MI][4], fBh[4][2], fBl[4][2];
#pragma unroll
            for (int mi = 0; mi < MI; mi++) {
                int krow = ks * 16 + (lane & 7) + ((lane >> 4) << 3);
                int moff = base_m + mi * 16 + ((lane >> 3) & 1) * 8;
                int off = krow * LDAA + moff;
                ldsm4t(fAh[mi], s32(Ah + off));
                ldsm4t(fAl[mi], s32(Al + off));
            }
#pragma unroll
            for (int p = 0; p < 2; p++) {
                int krow = ks * 16 + (lane & 7) + (((lane >> 3) & 1) << 3);
                int noff = base_n + p * 16 + ((lane >> 4) << 3);
                int off = krow * LDB + noff;
                uint32_t r[4];
                ldsm4t(r, s32(Bh + off));
                fBh[2 * p][0] = r[0]; fBh[2 * p][1] = r[1];
                fBh[2 * p + 1][0] = r[2]; fBh[2 * p + 1][1] = r[3];
                ldsm4t(r, s32(Bl + off));
                fBl[2 * p][0] = r[0]; fBl[2 * p][1] = r[1];
                fBl[2 * p + 1][0] = r[2]; fBl[2 * p + 1][1] = r[3];
            }
#pragma unroll
            for (int mi = 0; mi < MI; mi++)
#pragma unroll
                for (int j = 0; j < 4; j++) mma16(acc[mi][j], fAh[mi], fBh[j]);
#pragma unroll
            for (int mi = 0; mi < MI; mi++)
#pragma unroll
                for (int j = 0; j < 4; j++) mma16(acc[mi][j], fAl[mi], fBh[j]);
#pragma unroll
            for (int mi = 0; mi < MI; mi++)
#pragma unroll
                for (int j = 0; j < 4; j++) mma16(acc[mi][j], fAh[mi], fBl[j]);
        }
    };

    g2r(0); r2s(0); __syncthreads();
    for (int ch = 0; ch < NCH; ch++) {
        const int s = ch & 1;
        if (ch + 1 < NCH) g2r(ch + 1);
        compute(s);
        if (ch + 1 < NCH) r2s(s ^ 1);
        __syncthreads();
    }

#pragma unroll
    for (int mi = 0; mi < MI; mi++)
#pragma unroll
        for (int j = 0; j < 4; j++)
#pragma unroll
            for (int hh = 0; hh < 2; hh++) {
                int c = base_m + mi * 16 + (lane >> 2) + hh * 8;
                int h = h0 + base_n + j * 8 + 2 * (lane & 3);
                if (c < CC)
                    *(float2*)(Out + ((size_t)b * CC + c) * HH + h)
                        = make_float2(acc[mi][j][2 * hh], acc[mi][j][2 * hh + 1]);
            }
}

// ============================================================================
// Fill-at-(len-1) + avgpool3 (count_include_pad=False) + softmax + mask.
// ============================================================================
__global__ __launch_bounds__(128) void pool_softmax_kernel(const void* __restrict__ lens_raw,
                                                           float* __restrict__ attn,
                                                           float* __restrict__ smooth) {
    const int b = blockIdx.y;
    const int l0 = blockIdx.x * 128;
    const int len = load_len(lens_raw, b);

    __shared__ float s[130][CC];
    const int tid = threadIdx.x;

    for (int i = tid; i < 130 * CC; i += 128) {
        int rr = i / CC, c = i - rr * CC;
        int l = l0 - 1 + rr;
        l = max(0, min(l, LL - 1));
        int src = min(l, len - 1);
        s[rr][c] = g_P3[((size_t)b * LL + src) * CC + c];
    }
    __syncthreads();

    const int l = l0 + tid;
    const bool hasL = (l > 0), hasR = (l < LL - 1);
    const float inv = 1.0f / (float)(1 + (hasL ? 1 : 0) + (hasR ? 1 : 0));
    const int rr = tid + 1;

    float v[CC];
    float mx = -1e30f;
#pragma unroll
    for (int c = 0; c < CC; c++) {
        float t = s[rr][c];
        if (hasL) t += s[rr - 1][c];
        if (hasR) t += s[rr + 1][c];
        t *= inv;
        v[c] = t;
        mx = fmaxf(mx, t);
    }
    const size_t base = ((size_t)b * LL + l) * CC;
    float sum = 0.f;
#pragma unroll
    for (int c = 0; c < CC; c++) {
        smooth[base + c] = v[c];
        float e = expf(v[c] - mx);
        v[c] = e;
        sum += e;
    }
    const float isum = (l < len) ? (1.0f / sum) : 0.0f;
#pragma unroll
    for (int c = 0; c < CC; c++) attn[base + c] = v[c] * isum;
}

// ============================================================================
extern "C" void kernel_launch(void* const* d_in, const int* in_sizes, int n_in,
                              void* d_out, int out_size) {
    const float* keys = (const float*)d_in[0];
    const float* vals = (const float*)d_in[1];
    const void*  lens = d_in[2];
    const float* W1 = (const float*)d_in[3];
    const float* W2 = (const float*)d_in[4];
    const float* W3 = (const float*)d_in[5];

    float* attn   = (float*)d_out;                        // (B, L, C)
    float* cls    = attn + (size_t)BB * LL * CC;          // (B, C, H)
    float* smooth = cls + (size_t)BB * CC * HH;           // (B, L, C)

    __half *w1h, *w2h;
    cudaGetSymbolAddress((void**)&w1h, g_W1h);
    cudaGetSymbolAddress((void**)&w2h, g_W2h);

    // smem (bytes): 4 B-stages (hi only) + A-stages (2 for MODE0, 4 otherwise)
    const int SM0 = (4 * 128 * 24 + 2 * 2 * 256 * 24) * 2;  //  73728
    const int SM1 = (4 * 128 * 24 + 4 * 2 * 256 * 24) * 2;  // 122880
    const int SM2 = (4 * 64 * 24 + 4 * 2 * 256 * 24) * 2;   // 110592
    const int SMC = 2 * (2 * 32 * 72 + 2 * 32 * 136) * 2;   //  53248
    cudaFuncSetAttribute(gemm_f<0>, cudaFuncAttributeMaxDynamicSharedMemorySize, SM0);
    cudaFuncSetAttribute(gemm_f<1>, cudaFuncAttributeMaxDynamicSharedMemorySize, SM1);
    cudaFuncSetAttribute(gemm_f<2>, cudaFuncAttributeMaxDynamicSharedMemorySize, SM2);
    cudaFuncSetAttribute(classmm_h, cudaFuncAttributeMaxDynamicSharedMemorySize, SMC);

    split_hi_kernel<<<256, 256>>>(W1, w1h, HH * HH / 4);
    split_hi_kernel<<<256, 256>>>(W2, w2h, HH * HH / 4);
    split_w3_kernel<<<32, 256>>>(W3);

    gemm_f<0><<<dim3(HH / 128, MM / 256), 256, SM0>>>(keys);
    gemm_f<1><<<dim3(HH / 128, MM / 256), 256, SM1>>>(nullptr);
    gemm_f<2><<<dim3(1, MM / 256), 256, SM2>>>(nullptr);
    pool_softmax_kernel<<<dim3(LL / 128, BB), 128>>>(lens, attn, smooth);
    classmm_h<<<dim3(HH / 128, BB), 256, SMC>>>(attn, vals, cls);
}

// round 14
// speedup vs baseline: 1.4233x; 1.1254x over previous
#include <cuda_runtime.h>
#include <cuda_fp16.h>
#include <cstdint>
#include <math.h>

#define BB 32
#define LL 2048
#define HH 512
#define CC 50
#define MM (BB * LL)   // 65536

// ---- scratch: half planes (allocation-free). A-side hi+lo; weights hi only. ----
__device__ __align__(16) __half g_P1h[(size_t)MM * HH];
__device__ __align__(16) __half g_P1l[(size_t)MM * HH];
__device__ __align__(16) __half g_P12h[(size_t)MM * HH];
__device__ __align__(16) __half g_P12l[(size_t)MM * HH];
__device__ __align__(16) __half g_W1h[HH * HH];
__device__ __align__(16) __half g_W2h[HH * HH];
__device__ __align__(16) __half g_W3h[64 * HH];
__device__ __align__(16) float  g_P3[(size_t)MM * CC];

// ============================================================================
// helpers
// ============================================================================
__device__ __forceinline__ uint32_t s32(const void* p) {
    return (uint32_t)__cvta_generic_to_shared(p);
}
__device__ __forceinline__ void cp16(uint32_t saddr, const void* gaddr) {
    asm volatile("cp.async.cg.shared.global [%0], [%1], 16;" :: "r"(saddr), "l"(gaddr));
}
__device__ __forceinline__ void cp_commit() {
    asm volatile("cp.async.commit_group;" ::: "memory");
}
template <int N>
__device__ __forceinline__ void cp_wait() {
    asm volatile("cp.async.wait_group %0;" :: "n"(N) : "memory");
}
__device__ __forceinline__ void ldsm4(uint32_t* r, uint32_t a) {
    asm volatile("ldmatrix.sync.aligned.m8n8.x4.shared.b16 {%0,%1,%2,%3}, [%4];"
        : "=r"(r[0]), "=r"(r[1]), "=r"(r[2]), "=r"(r[3]) : "r"(a));
}
__device__ __forceinline__ void ldsm4t(uint32_t* r, uint32_t a) {
    asm volatile("ldmatrix.sync.aligned.m8n8.x4.trans.shared.b16 {%0,%1,%2,%3}, [%4];"
        : "=r"(r[0]), "=r"(r[1]), "=r"(r[2]), "=r"(r[3]) : "r"(a));
}
__device__ __forceinline__ void mma16(float* d, const uint32_t* a, const uint32_t* b) {
    asm volatile("mma.sync.aligned.m16n8k16.row.col.f32.f16.f16.f32 "
        "{%0,%1,%2,%3},{%4,%5,%6,%7},{%8,%9},{%0,%1,%2,%3};"
        : "+f"(d[0]), "+f"(d[1]), "+f"(d[2]), "+f"(d[3])
        : "r"(a[0]), "r"(a[1]), "r"(a[2]), "r"(a[3]), "r"(b[0]), "r"(b[1]));
}
__device__ __forceinline__ uint32_t packh2(float a, float b) {
    __half2 h = __floats2half2_rn(a, b);
    return *reinterpret_cast<uint32_t*>(&h);
}
__device__ __forceinline__ void hsplit(float x, float& hf, float& lf) {
    hf = __half2float(__float2half_rn(x));
    lf = x - hf;
}
__device__ __forceinline__ float tanh_fast(float x) {
    float xc = fminf(fmaxf(x, -15.f), 15.f);
    float e = __expf(2.f * xc);
    return 1.f - __fdividef(2.f, e + 1.f);
}
// sent_lens may be int32 or int64. lens in [1, 2048]: for int64 LE, word[1]=0.
__device__ __forceinline__ int load_len(const void* p, int b) {
    const int* w = (const int*)p;
    bool is64 = (w[1] == 0);
    return is64 ? w[2 * b] : w[b];
}

// ============================================================================
// pre-pass: weights -> half hi plane only
// ============================================================================
__global__ void split_hi_kernel(const float* __restrict__ src, __half* __restrict__ h, int n4) {
    for (int i = blockIdx.x * blockDim.x + threadIdx.x; i < n4; i += gridDim.x * blockDim.x) {
        float4 x = ((const float4*)src)[i];
        *(uint2*)(h + 4 * i) = make_uint2(packh2(x.x, x.y), packh2(x.z, x.w));
    }
}
__global__ void split_w3_kernel(const float* __restrict__ src) {
    int i = blockIdx.x * blockDim.x + threadIdx.x;
    if (i >= 64 * HH / 4) return;
    int row = (4 * i) / HH;
    float4 x = make_float4(0.f, 0.f, 0.f, 0.f);
    if (row < CC) x = ((const float4*)src)[i];
    *(uint2*)(g_W3h + 4 * i) = make_uint2(packh2(x.x, x.y), packh2(x.z, x.w));
}

// ============================================================================
// fp16 2-term GEMM (A split hi/lo, B hi only), 128xNT CTA tiles, 2 CTAs/SM.
// D(128 x NT) = A(128 x 512) * W^T ; KC = 16, 32 chunks.
// MODE 0: A = keys fp32 (LDG+split), B = g_W1h, epi: split(tanh(D)) -> g_P1
// MODE 1: A = g_P1 planes,           B = g_W2h, epi: split(P1+tanh(D)) -> g_P12
// MODE 2: A = g_P12 planes, NT=64,   B = g_W3h, epi: D -> g_P3 (c < 50)
// Warp layout: MODE 0/1: 4m x 2n of 32x64 tiles (MI=2,NJ=8);
//              MODE 2:   8m x 1n of 16x64 tiles (MI=1,NJ=8).
// ============================================================================
template <int MODE>
__global__ __launch_bounds__(256, 2) void gemm_f(const float* __restrict__ keys) {
    constexpr int NT = (MODE == 2) ? 64 : 128;
    constexpr int KC = 16;
    constexpr int NCH = HH / KC;          // 32
    constexpr int LD = KC + 8;            // 24 halfs (48B rows, ldsm bank-clean)
    constexpr int BST = NT * LD;          // halfs per B stage (hi only)
    constexpr int ASTF = 2 * 128 * LD;    // halfs per A stage (hi+lo)
    constexpr int MI = (MODE == 2) ? 1 : 2;
    constexpr int NJ = 8;
    constexpr int NP = NT / 16;           // B ldsm count (4 or 8... NT/16: 8 for 128? no: 4 per 64)

    extern __shared__ __align__(16) __half sm[];
    __half* Abase = sm + 4 * BST;

    const int tid = threadIdx.x;
    const int lane = tid & 31;
    const int warp = tid >> 5;
    const int row0 = blockIdx.y * 128;
    const int col0 = blockIdx.x * NT;

    const int base_m = (MODE == 2) ? warp * 16 : (warp >> 1) * 32;
    const int base_n = (MODE == 2) ? 0 : (warp & 1) * 64;

    const __half* gAh = (MODE == 1) ? g_P1h : g_P12h;
    const __half* gAl = (MODE == 1) ? g_P1l : g_P12l;
    const __half* gBh = (MODE == 0) ? g_W1h : (MODE == 1) ? g_W2h : g_W3h;

    float acc[MI][NJ][4] = {};
    float4 aR[2];                          // MODE 0 A prefetch registers

    auto loadB = [&](int ch, int s) {
        const int k0 = ch * KC;
        __half* Bh = sm + s * BST;
        if (NT == 128 || tid < 128) {
            int row = (tid >> 1) & (NT - 1), seg = tid & 1;
            size_t g = (size_t)(col0 + row) * HH + k0 + seg * 8;
            cp16(s32(Bh + row * LD + seg * 8), gBh + g);
        }
    };
    auto loadA = [&](int ch, int s) {       // MODE 1/2 only
        const int k0 = ch * KC;
        __half* Ah = Abase + s * ASTF;
        __half* Al = Ah + 128 * LD;
        int row = tid >> 1, seg = tid & 1;
        size_t g = (size_t)(row0 + row) * HH + k0 + seg * 8;
        cp16(s32(Ah + row * LD + seg * 8), gAh + g);
        cp16(s32(Al + row * LD + seg * 8), gAl + g);
    };
    auto g2rA = [&](int ch) {               // MODE 0 only
        const int k0 = ch * KC;
#pragma unroll
        for (int i = 0; i < 2; i++) {
            int f = i * 256 + tid, row = f >> 2, seg = f & 3;
            aR[i] = *(const float4*)(keys + (size_t)(row0 + row) * HH + k0 + seg * 4);
        }
    };
    auto r2sA = [&](int s) {                // MODE 0 only
        __half* Ah = Abase + s * ASTF;
        __half* Al = Ah + 128 * LD;
#pragma unroll
        for (int i = 0; i < 2; i++) {
            int f = i * 256 + tid, row = f >> 2, seg = f & 3;
            float h0, l0, h1, l1, h2, l2, h3, l3;
            hsplit(aR[i].x, h0, l0); hsplit(aR[i].y, h1, l1);
            hsplit(aR[i].z, h2, l2); hsplit(aR[i].w, h3, l3);
            *(uint2*)(Ah + row * LD + seg * 4) = make_uint2(packh2(h0, h1), packh2(h2, h3));
            *(uint2*)(Al + row * LD + seg * 4) = make_uint2(packh2(l0, l1), packh2(l2, l3));
        }
    };

    auto compute = [&](int sB, int sA) {
        const __half* Bh0 = sm + sB * BST;
        const __half* Ah0 = Abase + sA * ASTF;
        const __half* Al0 = Ah0 + 128 * LD;
        uint32_t fAh[MI][4], fAl[MI][4], bh[4][4];
#pragma unroll
        for (int mi = 0; mi < MI; mi++) {
            int row = base_m + mi * 16 + (lane & 15);
            int off = row * LD + ((lane >> 4) << 3);
            ldsm4(fAh[mi], s32(Ah0 + off));
            ldsm4(fAl[mi], s32(Al0 + off));
        }
#pragma unroll
        for (int p = 0; p < 4; p++) {
            int n = base_n + p * 16 + (lane & 7) + ((lane >> 4) << 3);
            int off = n * LD + (((lane >> 3) & 1) << 3);
            ldsm4(bh[p], s32(Bh0 + off));
        }
        // term 1: Ah*Bh — independent accumulators
#pragma unroll
        for (int mi = 0; mi < MI; mi++)
#pragma unroll
            for (int p = 0; p < 4; p++) {
                mma16(acc[mi][2 * p], fAh[mi], bh[p]);
                mma16(acc[mi][2 * p + 1], fAh[mi], bh[p] + 2);
            }
        // term 2: Al*Bh
#pragma unroll
        for (int mi = 0; mi < MI; mi++)
#pragma unroll
            for (int p = 0; p < 4; p++) {
                mma16(acc[mi][2 * p], fAl[mi], bh[p]);
                mma16(acc[mi][2 * p + 1], fAl[mi], bh[p] + 2);
            }
    };

    // prologue: 3 chunk-groups in flight; MODE 0 pre-stages A(0)
#pragma unroll
    for (int s = 0; s < 3; s++) {
        if (MODE != 0) loadA(s, s);
        loadB(s, s);
        cp_commit();
    }
    if (MODE == 0) { g2rA(0); r2sA(0); }

    for (int ch = 0; ch < NCH; ch++) {
        cp_wait<2>();
        __syncthreads();
        if (ch + 3 < NCH) {
            if (MODE != 0) loadA(ch + 3, (ch + 3) & 3);
            loadB(ch + 3, (ch + 3) & 3);
        }
        cp_commit();
        if (MODE == 0 && ch + 1 < NCH) g2rA(ch + 1);
        compute(ch & 3, (MODE == 0) ? (ch & 1) : (ch & 3));
        if (MODE == 0 && ch + 1 < NCH) r2sA((ch + 1) & 1);
    }

    // ---- epilogue ----
#pragma unroll
    for (int mi = 0; mi < MI; mi++)
#pragma unroll
        for (int j = 0; j < NJ; j++)
#pragma unroll
            for (int hh = 0; hh < 2; hh++) {
                int r = row0 + base_m + mi * 16 + (lane >> 2) + hh * 8;
                int c = col0 + base_n + j * 8 + 2 * (lane & 3);
                float v0 = acc[mi][j][2 * hh], v1 = acc[mi][j][2 * hh + 1];
                if constexpr (MODE == 2) {
                    if (c < CC)
                        *(float2*)(g_P3 + (size_t)r * CC + c) = make_float2(v0, v1);
                } else {
                    size_t off = (size_t)r * HH + c;
                    float t0, t1;
                    if constexpr (MODE == 0) {
                        t0 = tanh_fast(v0); t1 = tanh_fast(v1);
                    } else {
                        float2 pf = __half22float2(*(const __half2*)(g_P1h + off));
                        float2 qf = __half22float2(*(const __half2*)(g_P1l + off));
                        t0 = (pf.x + qf.x) + tanh_fast(v0);
                        t1 = (pf.y + qf.y) + tanh_fast(v1);
                    }
                    float h0, l0, h1, l1;
                    hsplit(t0, h0, l0); hsplit(t1, h1, l1);
                    __half* oh = (MODE == 0) ? g_P1h : g_P12h;
                    __half* ol = (MODE == 0) ? g_P1l : g_P12l;
                    *(uint32_t*)(oh + off) = packh2(h0, h1);
                    *(uint32_t*)(ol + off) = packh2(l0, l1);
                }
            }
}

// ============================================================================
// class_inputs[b,c,h] = sum_l attn[b,l,c] * V[b,l,h]  (full 3-term, unchanged)
// ============================================================================
__global__ __launch_bounds__(256, 1) void classmm_h(const float* __restrict__ attn,
                                                    const float* __restrict__ V,
                                                    float* __restrict__ Out) {
    constexpr int KC = 32;
    constexpr int NCH = LL / KC;    // 64
    constexpr int LDAA = 72;
    constexpr int LDB = 136;
    constexpr int A_ST = KC * LDAA;
    constexpr int B_ST = KC * LDB;
    constexpr int STAGE = 2 * A_ST + 2 * B_ST;
    constexpr int MI = 2;

    extern __shared__ __align__(16) __half sm[];
    const int tid = threadIdx.x, lane = tid & 31, warp = tid >> 5;
    const int b = blockIdx.y;
    const int h0 = blockIdx.x * 128;
    const int base_m = (warp >> 2) * 32;
    const int base_n = (warp & 3) * 32;

    float acc[MI][4][4] = {};
    float2 aA[4]; float4 aB[4];
    const int m2 = tid & 31;
    const int kkA = tid >> 5;

    auto g2r = [&](int ch) {
        const int k0 = ch * KC;
#pragma unroll
        for (int i = 0; i < 4; i++) {
            int kk = kkA + i * 8;
            float2 x = make_float2(0.f, 0.f);
            if (m2 < 25) x = *(const float2*)(attn + ((size_t)b * LL + k0 + kk) * CC + m2 * 2);
            aA[i] = x;
        }
#pragma unroll
        for (int i = 0; i < 4; i++) {
            int f = i * 256 + tid, n4 = f & 31, kk = f >> 5;
            aB[i] = *(const float4*)(V + ((size_t)b * LL + k0 + kk) * HH + h0 + n4 * 4);
        }
    };
    auto r2s = [&](int s) {
        __half* Ah = sm + s * STAGE;
        __half* Al = Ah + A_ST;
        __half* Bh = Al + A_ST;
        __half* Bl = Bh + B_ST;
#pragma unroll
        for (int i = 0; i < 4; i++) {
            int kk = kkA + i * 8;
            float h0_, l0_, h1_, l1_;
            hsplit(aA[i].x, h0_, l0_); hsplit(aA[i].y, h1_, l1_);
            *(uint32_t*)(Ah + kk * LDAA + m2 * 2) = packh2(h0_, h1_);
            *(uint32_t*)(Al + kk * LDAA + m2 * 2) = packh2(l0_, l1_);
        }
#pragma unroll
        for (int i = 0; i < 4; i++) {
            int f = i * 256 + tid, n4 = f & 31, kk = f >> 5;
            float h0_, l0_, h1_, l1_, h2_, l2_, h3_, l3_;
            hsplit(aB[i].x, h0_, l0_); hsplit(aB[i].y, h1_, l1_);
            hsplit(aB[i].z, h2_, l2_); hsplit(aB[i].w, h3_, l3_);
            *(uint2*)(Bh + kk * LDB + n4 * 4) = make_uint2(packh2(h0_, h1_), packh2(h2_, h3_));
            *(uint2*)(Bl + kk * LDB + n4 * 4) = make_uint2(packh2(l0_, l1_), packh2(l2_, l3_));
        }
    };
    auto compute = [&](int s) {
        const __half* Ah = sm + s * STAGE;
        const __half* Al = Ah + A_ST;
        const __half* Bh = Al + A_ST;
        const __half* Bl = Bh + B_ST;
#pragma unroll
        for (int ks = 0; ks < 2; ks++) {
            uint32_t fAh[MI][4], fAl[MI][4], fBh[4][2], fBl[4][2];
#pragma unroll
            for (int mi = 0; mi < MI; mi++) {
                int krow = ks * 16 + (lane & 7) + ((lane >> 4) << 3);
                int moff = base_m + mi * 16 + ((lane >> 3) & 1) * 8;
                int off = krow * LDAA + moff;
                ldsm4t(fAh[mi], s32(Ah + off));
                ldsm4t(fAl[mi], s32(Al + off));
            }
#pragma unroll
            for (int p = 0; p < 2; p++) {
                int krow = ks * 16 + (lane & 7) + (((lane >> 3) & 1) << 3);
                int noff = base_n + p * 16 + ((lane >> 4) << 3);
                int off = krow * LDB + noff;
                uint32_t r[4];
                ldsm4t(r, s32(Bh + off));
                fBh[2 * p][0] = r[0]; fBh[2 * p][1] = r[1];
                fBh[2 * p + 1][0] = r[2]; fBh[2 * p + 1][1] = r[3];
                ldsm4t(r, s32(Bl + off));
                fBl[2 * p][0] = r[0]; fBl[2 * p][1] = r[1];
                fBl[2 * p + 1][0] = r[2]; fBl[2 * p + 1][1] = r[3];
            }
#pragma unroll
            for (int mi = 0; mi < MI; mi++)
#pragma unroll
                for (int j = 0; j < 4; j++) mma16(acc[mi][j], fAh[mi], fBh[j]);
#pragma unroll
            for (int mi = 0; mi < MI; mi++)
#pragma unroll
                for (int j = 0; j < 4; j++) mma16(acc[mi][j], fAl[mi], fBh[j]);
#pragma unroll
            for (int mi = 0; mi < MI; mi++)
#pragma unroll
                for (int j = 0; j < 4; j++) mma16(acc[mi][j], fAh[mi], fBl[j]);
        }
    };

    g2r(0); r2s(0); __syncthreads();
    for (int ch = 0; ch < NCH; ch++) {
        const int s = ch & 1;
        if (ch + 1 < NCH) g2r(ch + 1);
        compute(s);
        if (ch + 1 < NCH) r2s(s ^ 1);
        __syncthreads();
    }

#pragma unroll
    for (int mi = 0; mi < MI; mi++)
#pragma unroll
        for (int j = 0; j < 4; j++)
#pragma unroll
            for (int hh = 0; hh < 2; hh++) {
                int c = base_m + mi * 16 + (lane >> 2) + hh * 8;
                int h = h0 + base_n + j * 8 + 2 * (lane & 3);
                if (c < CC)
                    *(float2*)(Out + ((size_t)b * CC + c) * HH + h)
                        = make_float2(acc[mi][j][2 * hh], acc[mi][j][2 * hh + 1]);
            }
}

// ============================================================================
// Fill-at-(len-1) + avgpool3 (count_include_pad=False) + softmax + mask.
// ============================================================================
__global__ __launch_bounds__(128) void pool_softmax_kernel(const void* __restrict__ lens_raw,
                                                           float* __restrict__ attn,
                                                           float* __restrict__ smooth) {
    const int b = blockIdx.y;
    const int l0 = blockIdx.x * 128;
    const int len = load_len(lens_raw, b);

    __shared__ float s[130][CC];
    const int tid = threadIdx.x;

    for (int i = tid; i < 130 * CC; i += 128) {
        int rr = i / CC, c = i - rr * CC;
        int l = l0 - 1 + rr;
        l = max(0, min(l, LL - 1));
        int src = min(l, len - 1);
        s[rr][c] = g_P3[((size_t)b * LL + src) * CC + c];
    }
    __syncthreads();

    const int l = l0 + tid;
    const bool hasL = (l > 0), hasR = (l < LL - 1);
    const float inv = 1.0f / (float)(1 + (hasL ? 1 : 0) + (hasR ? 1 : 0));
    const int rr = tid + 1;

    float v[CC];
    float mx = -1e30f;
#pragma unroll
    for (int c = 0; c < CC; c++) {
        float t = s[rr][c];
        if (hasL) t += s[rr - 1][c];
        if (hasR) t += s[rr + 1][c];
        t *= inv;
        v[c] = t;
        mx = fmaxf(mx, t);
    }
    const size_t base = ((size_t)b * LL + l) * CC;
    float sum = 0.f;
#pragma unroll
    for (int c = 0; c < CC; c++) {
        smooth[base + c] = v[c];
        float e = expf(v[c] - mx);
        v[c] = e;
        sum += e;
    }
    const float isum = (l < len) ? (1.0f / sum) : 0.0f;
#pragma unroll
    for (int c = 0; c < CC; c++) attn[base + c] = v[c] * isum;
}

// ============================================================================
extern "C" void kernel_launch(void* const* d_in, const int* in_sizes, int n_in,
                              void* d_out, int out_size) {
    const float* keys = (const float*)d_in[0];
    const float* vals = (const float*)d_in[1];
    const void*  lens = d_in[2];
    const float* W1 = (const float*)d_in[3];
    const float* W2 = (const float*)d_in[4];
    const float* W3 = (const float*)d_in[5];

    float* attn   = (float*)d_out;                        // (B, L, C)
    float* cls    = attn + (size_t)BB * LL * CC;          // (B, C, H)
    float* smooth = cls + (size_t)BB * CC * HH;           // (B, L, C)

    __half *w1h, *w2h;
    cudaGetSymbolAddress((void**)&w1h, g_W1h);
    cudaGetSymbolAddress((void**)&w2h, g_W2h);

    // smem (bytes): 4 B-stages (hi only) + A-stages (2 for MODE0, 4 otherwise)
    const int SM0 = (4 * 128 * 24 + 2 * 2 * 128 * 24) * 2;  // 49152
    const int SM1 = (4 * 128 * 24 + 4 * 2 * 128 * 24) * 2;  // 73728
    const int SM2 = (4 * 64 * 24 + 4 * 2 * 128 * 24) * 2;   // 61440
    const int SMC = 2 * (2 * 32 * 72 + 2 * 32 * 136) * 2;   // 53248
    cudaFuncSetAttribute(gemm_f<0>, cudaFuncAttributeMaxDynamicSharedMemorySize, SM0);
    cudaFuncSetAttribute(gemm_f<1>, cudaFuncAttributeMaxDynamicSharedMemorySize, SM1);
    cudaFuncSetAttribute(gemm_f<2>, cudaFuncAttributeMaxDynamicSharedMemorySize, SM2);
    cudaFuncSetAttribute(classmm_h, cudaFuncAttributeMaxDynamicSharedMemorySize, SMC);

    split_hi_kernel<<<256, 256>>>(W1, w1h, HH * HH / 4);
    split_hi_kernel<<<256, 256>>>(W2, w2h, HH * HH / 4);
    split_w3_kernel<<<32, 256>>>(W3);

    gemm_f<0><<<dim3(HH / 128, MM / 128), 256, SM0>>>(keys);
    gemm_f<1><<<dim3(HH / 128, MM / 128), 256, SM1>>>(nullptr);
    gemm_f<2><<<dim3(1, MM / 128), 256, SM2>>>(nullptr);
    pool_softmax_kernel<<<dim3(LL / 128, BB), 128>>>(lens, attn, smooth);
    classmm_h<<<dim3(HH / 128, BB), 256, SMC>>>(attn, vals, cls);
}